// round 10
// baseline (speedup 1.0000x reference)
#include <cuda_runtime.h>
#include <math.h>

// Problem constants (fixed by setup_inputs)
#define Bc   4
#define Ec   16
#define Cc   24
#define HWc  262144            // 512*512
#define TILE 2048              // pixels per phase-1 tile

#define DELTA_VAR  0.75f
#define DELTA_DIST 2.0f
#define ALPHA_W 1.0f
#define BETA_W  1.0f
#define GAMMA_W 0.001f

#define GRID     512           // co-resident CTAs (148 SMs x 4 >= 512)
#define P2_TILES 1024          // phase-2 work-steal tiles (1024 px each)

// ---------------- device scratch (no allocation allowed) ----------------
// Zero at module load; the elected last CTA re-zeroes everything after use,
// so every graph replay sees identical initial state.
__device__ float g_sum[Bc * Cc * Ec];   // [b][c][e] cluster embedding sums
__device__ float g_cnt[Bc * Cc];        // [b][c]    pixel counts
__device__ float g_loss;                // accumulated loss
__device__ unsigned int g_done;         // phase-1 arrival counter
__device__ unsigned int g_q2;           // phase-2 work queue head
__device__ unsigned int g_ticket;       // last-CTA election for output+reset

// ---------------- fused kernel ----------------
// Phase 1 (static tile): privatized conflict-free shared accumulation of
// per-(b,c) sums/counts (thread (e,j) owns bank-aligned column e*16+j).
// Device-wide arrive+spin barrier (all 512 CTAs co-resident by construction:
// launch_bounds(256,4), smem 35KB*4 <= 228KB, grid 512 <= 148*4).
// Phase 2 (work-stealing queue): hinged-variance over 1024-px tiles with the
// proven 4x4-wave LDG.128 batching and ||x||^2 / x.mu ILP decomposition.
// CTA 0 adds distance+reg terms; elected last CTA writes out[0] and resets.
__global__ void __launch_bounds__(256, 4)
k_fused(const float* __restrict__ input, const int* __restrict__ target,
        float* __restrict__ out) {
    __shared__ float  acc[Cc * 256];        // 24 KB  (phase 1)
    __shared__ uchar4 lab4[TILE / 4];       // 2 KB
    __shared__ int    hist[Cc];
    __shared__ float  mu_t[Bc][Ec][Cc];     // 6 KB   (phase 2, all batches)
    __shared__ float  mnorm[Bc][Cc];        // ||mu||^2
    __shared__ float  rcv[Bc][Cc];          // 1/(cnt*B*C)
    __shared__ float  red[8];
    __shared__ unsigned int s_tile;

    const int tid = threadIdx.x;

    // ================= PHASE 1: sums + counts (static tile) =================
    {
        const int b     = blockIdx.x >> 7;          // 128 tiles per batch
        const int tile0 = (blockIdx.x & 127) * TILE;

        #pragma unroll
        for (int i = tid; i < Cc * 256; i += 256) acc[i] = 0.f;
        if (tid < Cc) hist[tid] = 0;
        __syncthreads();

        const int4* tgt4 = (const int4*)(target + b * HWc + tile0);
        #pragma unroll
        for (int i = tid; i < TILE / 4; i += 256) {
            int4 l = tgt4[i];
            lab4[i] = make_uchar4((unsigned char)l.x, (unsigned char)l.y,
                                  (unsigned char)l.z, (unsigned char)l.w);
            atomicAdd(&hist[l.x], 1); atomicAdd(&hist[l.y], 1);
            atomicAdd(&hist[l.z], 1); atomicAdd(&hist[l.w], 1);
        }
        __syncthreads();

        const int e = tid >> 4;
        const int j = tid & 15;
        const float4* src = (const float4*)(input + (size_t)b * Ec * HWc +
                                            (size_t)e * HWc + tile0);
        float* accej = acc + e * 16 + j;

        #pragma unroll 8
        for (int k = 0; k < TILE / 64; ++k) {
            float4 v = src[k * 16 + j];
            uchar4 l = lab4[k * 16 + j];
            accej[(int)l.x * 256] += v.x;
            accej[(int)l.y * 256] += v.y;
            accej[(int)l.z * 256] += v.z;
            accej[(int)l.w * 256] += v.w;
        }
        __syncthreads();

        for (int o = tid; o < Cc * Ec; o += 256) {   // o = c*16 + e
            float s = 0.f;
            #pragma unroll
            for (int jj = 0; jj < 16; ++jj) s += acc[o * 16 + jj];
            atomicAdd(&g_sum[b * Cc * Ec + o], s);
        }
        if (tid < Cc) atomicAdd(&g_cnt[b * Cc + tid], (float)hist[tid]);
    }

    // ================= device-wide barrier (all CTAs resident) ==============
    __threadfence();                      // release our g_sum/g_cnt updates
    __syncthreads();
    if (tid == 0) {
        atomicAdd(&g_done, 1u);
        while (atomicAdd(&g_done, 0u) < (unsigned)GRID) __nanosleep(64);
    }
    __syncthreads();
    __threadfence();                      // acquire others' updates

    // ================= build mean tables (all batches) in shared ============
    for (int i = tid; i < Bc * Cc * Ec; i += 256) {
        int b = i / (Cc * Ec);
        int r = i - b * (Cc * Ec);
        int c = r >> 4, e = r & 15;
        mu_t[b][e][c] = __ldcg(&g_sum[i]) / __ldcg(&g_cnt[b * Cc + c]);
    }
    __syncthreads();
    for (int i = tid; i < Bc * Cc; i += 256) {
        int b = i / Cc, c = i - b * Cc;
        float nsq = 0.f;
        #pragma unroll
        for (int e = 0; e < Ec; ++e) { float m = mu_t[b][e][c]; nsq += m * m; }
        mnorm[b][c] = nsq;
        rcv[b][c] = 1.0f / (__ldcg(&g_cnt[i]) * (float)(Bc * Cc));
    }
    __syncthreads();

    // ================= PHASE 2: hinged variance (work-stealing) =============
    float accv = 0.f;
    for (;;) {
        if (tid == 0) s_tile = atomicAdd(&g_q2, 1u);
        __syncthreads();
        const unsigned t = s_tile;
        __syncthreads();                  // s_tile consumed before next write
        if (t >= (unsigned)P2_TILES) break;

        const int b  = t >> 8;            // 256 tiles per batch
        const int pq = (int)(t & 255u) * 256 + tid;    // pixel-quad index
        const int4 l = *(const int4*)(target + b * HWc + pq * 4);
        const float* base = input + (size_t)b * Ec * HWc + pq * 4;

        float n0 = 0.f, n1 = 0.f, n2 = 0.f, n3 = 0.f;
        float p0 = 0.f, p1 = 0.f, p2 = 0.f, p3 = 0.f;

        #pragma unroll
        for (int w = 0; w < 4; ++w) {
            float4 v[4];
            #pragma unroll
            for (int e = 0; e < 4; ++e)
                v[e] = *(const float4*)(base + (size_t)(w * 4 + e) * HWc);
            #pragma unroll
            for (int e = 0; e < 4; ++e) {
                const float* m = &mu_t[b][w * 4 + e][0];
                n0 += v[e].x * v[e].x;  p0 += v[e].x * m[l.x];
                n1 += v[e].y * v[e].y;  p1 += v[e].y * m[l.y];
                n2 += v[e].z * v[e].z;  p2 += v[e].z * m[l.z];
                n3 += v[e].w * v[e].w;  p3 += v[e].w * m[l.w];
            }
        }

        float s0 = fmaxf(n0 - 2.f * p0 + mnorm[b][l.x], 0.f);
        float s1 = fmaxf(n1 - 2.f * p1 + mnorm[b][l.y], 0.f);
        float s2 = fmaxf(n2 - 2.f * p2 + mnorm[b][l.z], 0.f);
        float s3 = fmaxf(n3 - 2.f * p3 + mnorm[b][l.w], 0.f);

        float h0 = fmaxf(sqrtf(s0) - DELTA_VAR, 0.f);
        float h1 = fmaxf(sqrtf(s1) - DELTA_VAR, 0.f);
        float h2 = fmaxf(sqrtf(s2) - DELTA_VAR, 0.f);
        float h3 = fmaxf(sqrtf(s3) - DELTA_VAR, 0.f);

        accv += ALPHA_W * (h0 * h0 * rcv[b][l.x] + h1 * h1 * rcv[b][l.y] +
                           h2 * h2 * rcv[b][l.z] + h3 * h3 * rcv[b][l.w]);
    }

    // ---- CTA 0: distance + regularizer terms (from shared mu tables) ----
    if (blockIdx.x == 0) {
        for (int i = tid; i < Bc * Cc; i += 256) {
            int b = i / Cc, c = i - b * Cc;
            float nsq = mnorm[b][c];
            float regc = (nsq == 0.f) ? 0.f : sqrtf(nsq);
            accv += GAMMA_W * regc * (1.0f / (Cc * Bc));
        }
        for (int t = tid; t < Bc * Cc * Cc; t += 256) {
            int b  = t / (Cc * Cc);
            int rr = t - b * (Cc * Cc);
            int ci = rr / Cc, cj = rr - ci * Cc;
            if (ci != cj) {
                float s = 0.f;
                #pragma unroll
                for (int e = 0; e < Ec; ++e) {
                    float d = mu_t[b][e][ci] - mu_t[b][e][cj];
                    s += d * d;
                }
                float dist = (s == 0.f) ? 0.f : sqrtf(s);
                float hd = fmaxf(2.0f * DELTA_DIST - dist, 0.f);
                accv += BETA_W * hd * hd * (1.0f / ((float)Bc * Cc * (Cc - 1)));
            }
        }
    }

    // ---- block reduction -> single atomic into g_loss ----
    #pragma unroll
    for (int o = 16; o > 0; o >>= 1)
        accv += __shfl_down_sync(0xffffffffu, accv, o);
    if ((tid & 31) == 0) red[tid >> 5] = accv;
    __syncthreads();
    if (tid == 0) {
        float s = red[0];
        #pragma unroll
        for (int w = 1; w < 8; ++w) s += red[w];
        atomicAdd(&g_loss, s);
    }

    // ---- last-CTA election: publish out[0], reset scratch for replay ----
    __threadfence();
    __syncthreads();
    if (tid == 0)
        s_tile = (atomicAdd(&g_ticket, 1u) == (unsigned)(GRID - 1));
    __syncthreads();
    if (s_tile) {
        if (tid == 0) {
            out[0] = atomicAdd(&g_loss, 0.f);   // coherent L2 read of total
            g_loss = 0.f;
            g_done = 0u; g_q2 = 0u; g_ticket = 0u;
        }
        for (int i = tid; i < Bc * Cc * Ec; i += 256) g_sum[i] = 0.f;
        if (tid < Bc * Cc) g_cnt[tid] = 0.f;
    }
}

// ---------------- launch ----------------
extern "C" void kernel_launch(void* const* d_in, const int* in_sizes, int n_in,
                              void* d_out, int out_size) {
    const float* input  = (const float*)d_in[0];
    const int*   target = (const int*)d_in[1];
    float*       out    = (float*)d_out;

    k_fused<<<GRID, 256>>>(input, target, out);
}